// round 2
// baseline (speedup 1.0000x reference)
#include <cuda_runtime.h>
#include <cuda_bf16.h>

#define Bb 8
#define Nn 4096
#define Dd 64
#define Gg 32
#define Kk 16

// scratch for knn indices (n-local per batch)
__device__ int g_nbr[Bb * Nn * Kk];

// ---------------------------------------------------------------------------
// f32x2 packed-FMA helpers (sm_10x: FFMA2 only reachable via PTX fma.rn.f32x2)
// ---------------------------------------------------------------------------
__device__ __forceinline__ unsigned long long pack2(float a, float b) {
    unsigned long long r;
    asm("mov.b64 %0, {%1, %2};" : "=l"(r) : "f"(a), "f"(b));
    return r;
}
__device__ __forceinline__ unsigned long long fma2(unsigned long long a,
                                                   unsigned long long b,
                                                   unsigned long long c) {
    unsigned long long d;
    asm("fma.rn.f32x2 %0, %1, %2, %3;" : "=l"(d) : "l"(a), "l"(b), "l"(c));
    return d;
}
__device__ __forceinline__ float2 unpack2(unsigned long long v) {
    float2 f;
    asm("mov.b64 {%0, %1}, %2;" : "=f"(f.x), "=f"(f.y) : "l"(v));
    return f;
}

// ---------------------------------------------------------------------------
// Kernel 1: brute-force KNN, one thread per query, 16 nearest excl. self.
// Order within the 16 does not matter (downstream is mean/max over K).
// ---------------------------------------------------------------------------
__global__ __launch_bounds__(128) void knn_kernel(const float* __restrict__ pos) {
    const int bx = blockIdx.x;          // 256 blocks: 32 per batch
    const int b = bx >> 5;
    const int n = ((bx & 31) << 7) + threadIdx.x;   // query index in batch

    const float qx = pos[(b * Nn + n) * 3 + 0];
    const float qy = pos[(b * Nn + n) * 3 + 1];
    const float qz = pos[(b * Nn + n) * 3 + 2];
    const float sqn = __fadd_rn(__fadd_rn(__fmul_rn(qx, qx), __fmul_rn(qy, qy)),
                                __fmul_rn(qz, qz));

    float bd[16];
    int bi[16];
#pragma unroll
    for (int j = 0; j < 16; ++j) { bd[j] = 3.0e38f; bi[j] = 0; }
    float worst = 3.0e38f;
    int wslot = 0;

    __shared__ float4 tile[1024];

    for (int t0 = 0; t0 < Nn; t0 += 1024) {
        __syncthreads();
        for (int i = threadIdx.x; i < 1024; i += 128) {
            const float px = pos[(b * Nn + t0 + i) * 3 + 0];
            const float py = pos[(b * Nn + t0 + i) * 3 + 1];
            const float pz = pos[(b * Nn + t0 + i) * 3 + 2];
            const float sq = __fadd_rn(__fadd_rn(__fmul_rn(px, px), __fmul_rn(py, py)),
                                       __fmul_rn(pz, pz));
            tile[i] = make_float4(px, py, pz, sq);
        }
        __syncthreads();
#pragma unroll 4
        for (int i = 0; i < 1024; ++i) {
            const float4 c = tile[i];
            const int m = t0 + i;
            // dot via fma chain; dist = (sqn + sqm) - 2*dot (matches reference formula)
            float dot = __fmaf_rn(qx, c.x, 0.f);
            dot = __fmaf_rn(qy, c.y, dot);
            dot = __fmaf_rn(qz, c.z, dot);
            const float dist = __fsub_rn(__fadd_rn(sqn, c.w), __fmul_rn(2.0f, dot));
            if (dist < worst && m != n) {
#pragma unroll
                for (int j = 0; j < 16; ++j)
                    if (j == wslot) { bd[j] = dist; bi[j] = m; }
                worst = bd[0]; wslot = 0;
#pragma unroll
                for (int j = 1; j < 16; ++j)
                    if (bd[j] > worst) { worst = bd[j]; wslot = j; }
            }
        }
    }

#pragma unroll
    for (int j = 0; j < 16; ++j)
        g_nbr[(b * Nn + n) * 16 + j] = bi[j];
}

// ---------------------------------------------------------------------------
// Kernel 2: fully fused DenseEdgeConv. One block = 4 points (k' = 64 lanes).
// 512 threads. All intermediates in smem, neighbor-pairs packed into f32x2.
// ---------------------------------------------------------------------------
#define SROW 68                     // padded row stride (floats) for k'=64 tiles
#define P4 4                        // points per block

// smem partition sizes (floats)
#define OFF_W2    0
#define OFF_WMID  (OFF_W2 + 256 * 32)
#define OFF_WLAST (OFF_WMID + 96 * 32)
#define OFF_XN    (OFF_WLAST + 128 * 32)
#define OFF_YBAR  (OFF_XN + P4 * 64)
#define OFF_GATE  (OFF_YBAR + P4 * 128)
#define OFF_NID   (OFF_GATE + P4 * 128)
#define OFF_Y2    (OFF_NID + 64)
#define OFF_BUF   (OFF_Y2 + 128 * SROW)
#define SMEM_FLOATS (OFF_BUF + 256 * SROW)

__global__ __launch_bounds__(512, 1) void conv_kernel(
    const float* __restrict__ x,
    const float* __restrict__ W1, const float* __restrict__ b1,
    const float* __restrict__ W2, const float* __restrict__ b2,
    const float* __restrict__ Wmid, const float* __restrict__ bmid,
    const float* __restrict__ Wg, const float* __restrict__ bg,
    const float* __restrict__ Wlast, const float* __restrict__ blast,
    float* __restrict__ out)
{
    extern __shared__ float sm[];
    float* sW2 = sm + OFF_W2;
    float* sWmid = sm + OFF_WMID;
    float* sWlast = sm + OFF_WLAST;
    float* sXn = sm + OFF_XN;
    float* sYbar = sm + OFF_YBAR;
    float* sGate = sm + OFF_GATE;
    int* sNid = (int*)(sm + OFF_NID);
    float* sY2 = sm + OFF_Y2;       // [128][SROW]
    float* sBuf = sm + OFF_BUF;     // AT [192][SROW] then h1T [256][SROW]

    const int t = threadIdx.x;
    const int g0 = blockIdx.x * P4;         // global point base
    const int b = g0 >> 12;                 // g0 / 4096

    // ---- stage weights + xn + neighbor ids -------------------------------
    for (int i = t; i < 256 * 32; i += 512) sW2[i] = W2[i];
    for (int i = t; i < 96 * 32; i += 512) sWmid[i] = Wmid[i];
    for (int i = t; i < 128 * 32; i += 512) sWlast[i] = Wlast[i];
    if (t < 256) sXn[t] = x[(g0 + (t >> 6)) * 64 + (t & 63)];
    if (t < 64) sNid[t] = g_nbr[g0 * 16 + t];
    __syncthreads();

    // ---- gather neighbors, build AT (edge^T) and xn part of y2 -----------
    // AT[j][kk]: j<64 -> xn, 64..127 -> nbr, 128..191 -> nbr - xn
#pragma unroll
    for (int it = 0; it < 8; ++it) {
        const int idx = it * 512 + t;
        const int kk = idx >> 6;            // 0..63 neighbor slot
        const int c = idx & 63;             // feature
        const int p = kk >> 4;
        const float xnv = sXn[p * 64 + c];
        const float xv = x[(b * Nn + sNid[kk]) * 64 + c];
        sBuf[c * SROW + kk] = xnv;
        sBuf[(64 + c) * SROW + kk] = xv;
        sBuf[(128 + c) * SROW + kk] = xv - xnv;
        sY2[(64 + c) * SROW + kk] = xnv;    // xn rows of y2 (k-independent)
    }
    __syncthreads();

    // ---- GEMM1: h1[c][kk] = relu(b1[c] + sum_j AT[j][kk] * W1[j][c]) ------
    // thread tile: 2 columns (2*cp, 2*cp+1) x 16 k of point kpg (8 f32x2 pairs)
    {
        const int kpg = t >> 7;             // 0..3 (point) — constant per warp
        const int cp = t & 127;             // column pair
        unsigned long long acc0[8], acc1[8];
#pragma unroll
        for (int kp = 0; kp < 8; ++kp) { acc0[kp] = 0ull; acc1[kp] = 0ull; }

        const float* w1p = W1 + 2 * cp;
        const float* abase = sBuf + kpg * 16;
#pragma unroll 4
        for (int j = 0; j < 192; ++j) {
            const float2 w = *(const float2*)(w1p + j * 256);
            const unsigned long long wx = pack2(w.x, w.x);
            const unsigned long long wy = pack2(w.y, w.y);
            const float* arow = abase + j * SROW;
#pragma unroll
            for (int kp = 0; kp < 8; ++kp) {
                const unsigned long long a = *(const unsigned long long*)(arow + 2 * kp);
                acc0[kp] = fma2(a, wx, acc0[kp]);
                acc1[kp] = fma2(a, wy, acc1[kp]);
            }
        }
        __syncthreads();    // all AT reads done before overwriting sBuf with h1T
        const float2 bia = *(const float2*)(b1 + 2 * cp);
        float* h0 = sBuf + (2 * cp) * SROW + kpg * 16;
        float* h1r = sBuf + (2 * cp + 1) * SROW + kpg * 16;
#pragma unroll
        for (int kp = 0; kp < 8; ++kp) {
            float2 v0 = unpack2(acc0[kp]);
            float2 v1 = unpack2(acc1[kp]);
            v0.x = fmaxf(v0.x + bia.x, 0.f); v0.y = fmaxf(v0.y + bia.x, 0.f);
            v1.x = fmaxf(v1.x + bia.y, 0.f); v1.y = fmaxf(v1.y + bia.y, 0.f);
            *(float2*)(h0 + 2 * kp) = v0;
            *(float2*)(h1r + 2 * kp) = v1;
        }
    }
    __syncthreads();

    const int cout = t >> 4;                // 0..31
    const int kq = t & 15;                  // 0..15 -> 4 consecutive kk
    const int kk0 = kq << 2;

    // ---- GEMM2: h[cout][kk] = relu(b2 + sum_c h1[c][kk]*W2[c][cout]) ------
    {
        unsigned long long a0 = 0ull, a1 = 0ull;
#pragma unroll 4
        for (int c = 0; c < 256; ++c) {
            const ulonglong2 av = *(const ulonglong2*)(sBuf + c * SROW + kk0);
            const float w = sW2[(c << 5) + cout];
            const unsigned long long wp = pack2(w, w);
            a0 = fma2(av.x, wp, a0);
            a1 = fma2(av.y, wp, a1);
        }
        const float bb = b2[cout];
        float2 v0 = unpack2(a0), v1 = unpack2(a1);
        float4 r;
        r.x = fmaxf(v0.x + bb, 0.f); r.y = fmaxf(v0.y + bb, 0.f);
        r.z = fmaxf(v1.x + bb, 0.f); r.w = fmaxf(v1.y + bb, 0.f);
        *(float4*)(sY2 + (32 + cout) * SROW + kk0) = r;  // h rows of y2
    }
    __syncthreads();

    // ---- mid: m[cout][kk] = relu(bmid + sum_{j<96} y1[j][kk]*Wmid[j][cout])
    // y1 = rows 32..127 of y2 ([h, xn])
    {
        unsigned long long a0 = 0ull, a1 = 0ull;
#pragma unroll 4
        for (int j = 0; j < 96; ++j) {
            const ulonglong2 av = *(const ulonglong2*)(sY2 + (32 + j) * SROW + kk0);
            const float w = sWmid[(j << 5) + cout];
            const unsigned long long wp = pack2(w, w);
            a0 = fma2(av.x, wp, a0);
            a1 = fma2(av.y, wp, a1);
        }
        const float bb = bmid[cout];
        float2 v0 = unpack2(a0), v1 = unpack2(a1);
        float4 r;
        r.x = fmaxf(v0.x + bb, 0.f); r.y = fmaxf(v0.y + bb, 0.f);
        r.z = fmaxf(v1.x + bb, 0.f); r.w = fmaxf(v1.y + bb, 0.f);
        *(float4*)(sY2 + cout * SROW + kk0) = r;         // m rows of y2
    }
    __syncthreads();

    const int pp = t >> 7;                  // 0..3
    const int jj = t & 127;                 // 0..127

    // ---- gate: ybar = mean_k y2 ------------------------------------------
    {
        const float* row = sY2 + jj * SROW + pp * 16;
        float4 s0 = *(const float4*)(row + 0);
        float4 s1 = *(const float4*)(row + 4);
        float4 s2 = *(const float4*)(row + 8);
        float4 s3 = *(const float4*)(row + 12);
        float s = (s0.x + s0.y + s0.z + s0.w) + (s1.x + s1.y + s1.z + s1.w)
                + (s2.x + s2.y + s2.z + s2.w) + (s3.x + s3.y + s3.z + s3.w);
        sYbar[pp * 128 + jj] = s * (1.0f / 16.0f);
    }
    __syncthreads();

    // ---- gate = sigmoid(ybar @ Wg + bg) -----------------------------------
    {
        float a = 0.f;
        const float* yb = sYbar + pp * 128;
#pragma unroll 4
        for (int j = 0; j < 128; ++j)
            a = __fmaf_rn(yb[j], Wg[j * 128 + jj], a);
        a += bg[jj];
        sGate[pp * 128 + jj] = 1.0f / (1.0f + expf(-a));
    }
    __syncthreads();

    // ---- y3 = y2 * gate, plus max over k for channels 32..159 -------------
    {
        const float gv = sGate[pp * 128 + jj];
        float* row = sY2 + jj * SROW + pp * 16;
        float mx = -3.0e38f;
#pragma unroll
        for (int q = 0; q < 4; ++q) {
            float4 v = *(const float4*)(row + 4 * q);
            v.x *= gv; v.y *= gv; v.z *= gv; v.w *= gv;
            mx = fmaxf(mx, fmaxf(fmaxf(v.x, v.y), fmaxf(v.z, v.w)));
            *(float4*)(row + 4 * q) = v;
        }
        out[(g0 + pp) * 160 + 32 + jj] = mx;
    }
    __syncthreads();

    // ---- last: last[cout][kk] = blast + sum_j y3[j][kk]*Wlast[j][cout];
    //      out channels 0..31 = max_k last ---------------------------------
    {
        unsigned long long a0 = 0ull, a1 = 0ull;
#pragma unroll 4
        for (int j = 0; j < 128; ++j) {
            const ulonglong2 av = *(const ulonglong2*)(sY2 + j * SROW + kk0);
            const float w = sWlast[(j << 5) + cout];
            const unsigned long long wp = pack2(w, w);
            a0 = fma2(av.x, wp, a0);
            a1 = fma2(av.y, wp, a1);
        }
        const float bb = blast[cout];
        float2 v0 = unpack2(a0), v1 = unpack2(a1);
        float mx = fmaxf(fmaxf(v0.x + bb, v0.y + bb), fmaxf(v1.x + bb, v1.y + bb));
        // reduce over the 4 threads covering the 16 k of point p = kq>>2
        mx = fmaxf(mx, __shfl_xor_sync(0xffffffffu, mx, 1));
        mx = fmaxf(mx, __shfl_xor_sync(0xffffffffu, mx, 2));
        if ((kq & 3) == 0)
            out[(g0 + (kq >> 2)) * 160 + cout] = mx;
    }
}

// ---------------------------------------------------------------------------
extern "C" void kernel_launch(void* const* d_in, const int* in_sizes, int n_in,
                              void* d_out, int out_size) {
    const float* x = (const float*)d_in[0];
    const float* pos = (const float*)d_in[1];
    const float* W1 = (const float*)d_in[2];
    const float* b1 = (const float*)d_in[3];
    const float* W2 = (const float*)d_in[4];
    const float* b2 = (const float*)d_in[5];
    const float* Wmid = (const float*)d_in[6];
    const float* bmid = (const float*)d_in[7];
    const float* Wg = (const float*)d_in[8];
    const float* bg = (const float*)d_in[9];
    const float* Wlast = (const float*)d_in[10];
    const float* blast = (const float*)d_in[11];
    float* out = (float*)d_out;

    const int smem_bytes = SMEM_FLOATS * 4;
    cudaFuncSetAttribute(conv_kernel, cudaFuncAttributeMaxDynamicSharedMemorySize,
                         smem_bytes);

    knn_kernel<<<(Bb * Nn) / 128, 128>>>(pos);
    conv_kernel<<<(Bb * Nn) / P4, 512, smem_bytes>>>(
        x, W1, b1, W2, b2, Wmid, bmid, Wg, bg, Wlast, blast, out);
}

// round 3
// speedup vs baseline: 1.2997x; 1.2997x over previous
#include <cuda_runtime.h>
#include <cuda_bf16.h>

#define Bb 8
#define Nn 4096
#define Dd 64
#define Gg 32
#define Kk 16

typedef unsigned long long ull;

// scratch
__device__ int g_nbr[Bb * Nn * Kk];
__device__ float g_W1p[64 * 256];   // W1[0:64] - W1[128:192]   (x part)
__device__ float g_W1n[64 * 256];   // W1[64:128] + W1[128:192] (nbr part)

// ---------------------------------------------------------------------------
// f32x2 packed-FMA helpers
// ---------------------------------------------------------------------------
__device__ __forceinline__ ull pack2(float a, float b) {
    ull r;
    asm("mov.b64 %0, {%1, %2};" : "=l"(r) : "f"(a), "f"(b));
    return r;
}
__device__ __forceinline__ ull fma2(ull a, ull b, ull c) {
    ull d;
    asm("fma.rn.f32x2 %0, %1, %2, %3;" : "=l"(d) : "l"(a), "l"(b), "l"(c));
    return d;
}
__device__ __forceinline__ float2 unpack2(ull v) {
    float2 f;
    asm("mov.b64 {%0, %1}, %2;" : "=f"(f.x), "=f"(f.y) : "l"(v));
    return f;
}

// ---------------------------------------------------------------------------
// Kernel 0: fold the 3-way edge concat into two 64-row weight blocks
// ---------------------------------------------------------------------------
__global__ __launch_bounds__(256) void prep_kernel(const float* __restrict__ W1) {
    const int i = blockIdx.x * 256 + threadIdx.x;   // 0..16383
    const int j = i >> 8;
    const int c = i & 255;
    const float wa = W1[j * 256 + c];
    const float wb = W1[(64 + j) * 256 + c];
    const float wc = W1[(128 + j) * 256 + c];
    g_W1p[i] = wa - wc;
    g_W1n[i] = wb + wc;
}

// ---------------------------------------------------------------------------
// Kernel 1: brute-force KNN, one thread per query, 16 nearest excl. self.
// (identical math to the passing round-2 version)
// ---------------------------------------------------------------------------
__global__ __launch_bounds__(128) void knn_kernel(const float* __restrict__ pos) {
    const int bx = blockIdx.x;
    const int b = bx >> 5;
    const int n = ((bx & 31) << 7) + threadIdx.x;

    const float qx = pos[(b * Nn + n) * 3 + 0];
    const float qy = pos[(b * Nn + n) * 3 + 1];
    const float qz = pos[(b * Nn + n) * 3 + 2];
    const float sqn = __fadd_rn(__fadd_rn(__fmul_rn(qx, qx), __fmul_rn(qy, qy)),
                                __fmul_rn(qz, qz));

    float bd[16];
    int bi[16];
#pragma unroll
    for (int j = 0; j < 16; ++j) { bd[j] = 3.0e38f; bi[j] = 0; }
    float worst = 3.0e38f;
    int wslot = 0;

    __shared__ float4 tile[1024];

    for (int t0 = 0; t0 < Nn; t0 += 1024) {
        __syncthreads();
        for (int i = threadIdx.x; i < 1024; i += 128) {
            const float px = pos[(b * Nn + t0 + i) * 3 + 0];
            const float py = pos[(b * Nn + t0 + i) * 3 + 1];
            const float pz = pos[(b * Nn + t0 + i) * 3 + 2];
            const float sq = __fadd_rn(__fadd_rn(__fmul_rn(px, px), __fmul_rn(py, py)),
                                       __fmul_rn(pz, pz));
            tile[i] = make_float4(px, py, pz, sq);
        }
        __syncthreads();
#pragma unroll 4
        for (int i = 0; i < 1024; ++i) {
            const float4 c = tile[i];
            const int m = t0 + i;
            float dot = __fmaf_rn(qx, c.x, 0.f);
            dot = __fmaf_rn(qy, c.y, dot);
            dot = __fmaf_rn(qz, c.z, dot);
            const float dist = __fsub_rn(__fadd_rn(sqn, c.w), __fmul_rn(2.0f, dot));
            if (dist < worst && m != n) {
#pragma unroll
                for (int j = 0; j < 16; ++j)
                    if (j == wslot) { bd[j] = dist; bi[j] = m; }
                worst = bd[0]; wslot = 0;
#pragma unroll
                for (int j = 1; j < 16; ++j)
                    if (bd[j] > worst) { worst = bd[j]; wslot = j; }
            }
        }
    }

#pragma unroll
    for (int j = 0; j < 16; ++j)
        g_nbr[(b * Nn + n) * 16 + j] = bi[j];
}

// ---------------------------------------------------------------------------
// Kernel 2: fused DenseEdgeConv, 4 points (64 k-lanes) per block, 512 threads.
// ---------------------------------------------------------------------------
#define SROW 68
#define P4 4

#define OFF_NBRT 0
#define OFF_H1   (OFF_NBRT + 64 * SROW)
#define OFF_Y2   (OFF_H1 + 256 * SROW)
#define OFF_XH   (OFF_Y2 + 128 * SROW)
#define OFF_XN   (OFF_XH + P4 * 256)
#define OFF_YBAR (OFF_XN + P4 * 64)
#define OFF_GATE (OFF_YBAR + P4 * 128)
#define OFF_NID  (OFF_GATE + P4 * 128)
#define SMEM_FLOATS (OFF_NID + 64)

__global__ __launch_bounds__(512, 1) void conv_kernel(
    const float* __restrict__ x,
    const float* __restrict__ b1,
    const float* __restrict__ W2, const float* __restrict__ b2,
    const float* __restrict__ Wmid, const float* __restrict__ bmid,
    const float* __restrict__ Wg, const float* __restrict__ bg,
    const float* __restrict__ Wlast, const float* __restrict__ blast,
    float* __restrict__ out)
{
    extern __shared__ float sm[];
    float* sNbrT = sm + OFF_NBRT;   // [64 j][SROW k]
    float* sH1 = sm + OFF_H1;       // [256 c][SROW k]
    float* sY2 = sm + OFF_Y2;       // [128 ch][SROW k]: 0..31 m, 32..63 h, 64..127 xn
    float* sXh = sm + OFF_XH;       // [4 p][256 c]  x-part of GEMM1 preact (incl. b1)
    float* sXn = sm + OFF_XN;
    float* sYbar = sm + OFF_YBAR;
    float* sGate = sm + OFF_GATE;
    int* sNid = (int*)(sm + OFF_NID);

    const int t = threadIdx.x;
    const int g0 = blockIdx.x * P4;
    const int b = g0 >> 12;

    if (t < 256) sXn[t] = x[(g0 + (t >> 6)) * 64 + (t & 63)];
    if (t < 64) sNid[t] = g_nbr[g0 * 16 + t];
    __syncthreads();

    // ---- gather neighbor features (transposed) + xn rows of y2 -----------
#pragma unroll
    for (int it = 0; it < 8; ++it) {
        const int idx = it * 512 + t;
        const int kk = idx >> 6;
        const int c = idx & 63;
        sNbrT[c * SROW + kk] = x[(b * Nn + sNid[kk]) * 64 + c];
        sY2[(64 + c) * SROW + kk] = sXn[(kk >> 4) * 64 + c];
    }

    // ---- x-part of GEMM1: sXh[p][c] = b1[c] + xn[p] . W1p[:,c] -----------
    {
        const int p = t >> 7;
        const int c0 = t & 127;
        float a0 = 0.f, a1 = 0.f;
        const float* xnp = sXn + p * 64;
#pragma unroll 8
        for (int j = 0; j < 64; ++j) {
            const float xv = xnp[j];
            a0 = __fmaf_rn(xv, g_W1p[j * 256 + c0], a0);
            a1 = __fmaf_rn(xv, g_W1p[j * 256 + c0 + 128], a1);
        }
        sXh[p * 256 + c0] = a0 + b1[c0];
        sXh[p * 256 + c0 + 128] = a1 + b1[c0 + 128];
    }
    __syncthreads();

    // ---- GEMM1 (nbr part): h1[c][kk] = relu(sXh + nbrT^T @ W1n) ----------
    // thread: 8 cols (cg) x 4 k (kq); warp = 2 cg x 16 kq -> a-dedup in warp
    {
        const int cg = t >> 4;          // 0..31
        const int kq = t & 15;          // 0..15
        const int kk0 = kq << 2;
        const int p = kq >> 2;
        ull acc[4][4];
#pragma unroll
        for (int cp = 0; cp < 4; ++cp)
#pragma unroll
            for (int k = 0; k < 4; ++k) acc[cp][k] = 0ull;

        const float* wb2 = g_W1n + cg * 8;
        const float* ab = sNbrT + kk0;
#pragma unroll 4
        for (int j = 0; j < 64; ++j) {
            const float4 av = *(const float4*)(ab + j * SROW);
            const ull a0 = pack2(av.x, av.x);
            const ull a1 = pack2(av.y, av.y);
            const ull a2 = pack2(av.z, av.z);
            const ull a3 = pack2(av.w, av.w);
            const ulonglong2 w01 = *(const ulonglong2*)(wb2 + j * 256);
            const ulonglong2 w23 = *(const ulonglong2*)(wb2 + j * 256 + 4);
            acc[0][0] = fma2(a0, w01.x, acc[0][0]);
            acc[0][1] = fma2(a1, w01.x, acc[0][1]);
            acc[0][2] = fma2(a2, w01.x, acc[0][2]);
            acc[0][3] = fma2(a3, w01.x, acc[0][3]);
            acc[1][0] = fma2(a0, w01.y, acc[1][0]);
            acc[1][1] = fma2(a1, w01.y, acc[1][1]);
            acc[1][2] = fma2(a2, w01.y, acc[1][2]);
            acc[1][3] = fma2(a3, w01.y, acc[1][3]);
            acc[2][0] = fma2(a0, w23.x, acc[2][0]);
            acc[2][1] = fma2(a1, w23.x, acc[2][1]);
            acc[2][2] = fma2(a2, w23.x, acc[2][2]);
            acc[2][3] = fma2(a3, w23.x, acc[2][3]);
            acc[3][0] = fma2(a0, w23.y, acc[3][0]);
            acc[3][1] = fma2(a1, w23.y, acc[3][1]);
            acc[3][2] = fma2(a2, w23.y, acc[3][2]);
            acc[3][3] = fma2(a3, w23.y, acc[3][3]);
        }
#pragma unroll
        for (int cp = 0; cp < 4; ++cp) {
            const int ce = cg * 8 + cp * 2;
            const float xhe = sXh[p * 256 + ce];
            const float xho = sXh[p * 256 + ce + 1];
            const float2 u0 = unpack2(acc[cp][0]);
            const float2 u1 = unpack2(acc[cp][1]);
            const float2 u2 = unpack2(acc[cp][2]);
            const float2 u3 = unpack2(acc[cp][3]);
            float4 ev, ov;
            ev.x = fmaxf(u0.x + xhe, 0.f); ev.y = fmaxf(u1.x + xhe, 0.f);
            ev.z = fmaxf(u2.x + xhe, 0.f); ev.w = fmaxf(u3.x + xhe, 0.f);
            ov.x = fmaxf(u0.y + xho, 0.f); ov.y = fmaxf(u1.y + xho, 0.f);
            ov.z = fmaxf(u2.y + xho, 0.f); ov.w = fmaxf(u3.y + xho, 0.f);
            *(float4*)(sH1 + ce * SROW + kk0) = ev;
            *(float4*)(sH1 + (ce + 1) * SROW + kk0) = ov;
        }
    }
    __syncthreads();

    const int c = t & 31;               // output channel (32)
    const int kq = t >> 5;              // 0..15
    const int kk0 = kq << 2;

    // ---- GEMM2: h = relu(h1^T @ W2 + b2) -> sY2 rows 32..63 ---------------
    // warp = 32 c x 1 kq: a-load broadcast, weights 128B/warp from L1
    {
        ull a0 = 0ull, a1 = 0ull;
#pragma unroll 4
        for (int j = 0; j < 256; ++j) {
            const ulonglong2 av = *(const ulonglong2*)(sH1 + j * SROW + kk0);
            const float w = W2[(j << 5) + c];
            const ull wp = pack2(w, w);
            a0 = fma2(av.x, wp, a0);
            a1 = fma2(av.y, wp, a1);
        }
        const float bb = b2[c];
        const float2 v0 = unpack2(a0), v1 = unpack2(a1);
        float4 r;
        r.x = fmaxf(v0.x + bb, 0.f); r.y = fmaxf(v0.y + bb, 0.f);
        r.z = fmaxf(v1.x + bb, 0.f); r.w = fmaxf(v1.y + bb, 0.f);
        *(float4*)(sY2 + (32 + c) * SROW + kk0) = r;
    }
    __syncthreads();

    // ---- mid: m = relu([h, xn] @ Wmid + bmid) -> sY2 rows 0..31 ------------
    {
        ull a0 = 0ull, a1 = 0ull;
#pragma unroll 4
        for (int j = 0; j < 96; ++j) {
            const ulonglong2 av = *(const ulonglong2*)(sY2 + (32 + j) * SROW + kk0);
            const float w = Wmid[(j << 5) + c];
            const ull wp = pack2(w, w);
            a0 = fma2(av.x, wp, a0);
            a1 = fma2(av.y, wp, a1);
        }
        const float bb = bmid[c];
        const float2 v0 = unpack2(a0), v1 = unpack2(a1);
        float4 r;
        r.x = fmaxf(v0.x + bb, 0.f); r.y = fmaxf(v0.y + bb, 0.f);
        r.z = fmaxf(v1.x + bb, 0.f); r.w = fmaxf(v1.y + bb, 0.f);
        *(float4*)(sY2 + c * SROW + kk0) = r;
    }
    __syncthreads();

    const int pp = t >> 7;
    const int jj = t & 127;

    // ---- ybar = mean_k y2 --------------------------------------------------
    {
        const float* row = sY2 + jj * SROW + pp * 16;
        const float4 s0 = *(const float4*)(row + 0);
        const float4 s1 = *(const float4*)(row + 4);
        const float4 s2 = *(const float4*)(row + 8);
        const float4 s3 = *(const float4*)(row + 12);
        const float s = (s0.x + s0.y + s0.z + s0.w) + (s1.x + s1.y + s1.z + s1.w)
                      + (s2.x + s2.y + s2.z + s2.w) + (s3.x + s3.y + s3.z + s3.w);
        sYbar[pp * 128 + jj] = s * (1.0f / 16.0f);
    }
    __syncthreads();

    // ---- gate = sigmoid(ybar @ Wg + bg) ------------------------------------
    {
        float a = 0.f;
        const float* yb = sYbar + pp * 128;
#pragma unroll 4
        for (int j = 0; j < 128; ++j)
            a = __fmaf_rn(yb[j], Wg[j * 128 + jj], a);
        a += bg[jj];
        sGate[pp * 128 + jj] = 1.0f / (1.0f + expf(-a));
    }
    __syncthreads();

    // ---- y2 *= gate; out channels 32..159 = max_k ---------------------------
    {
        const float gv = sGate[pp * 128 + jj];
        float* row = sY2 + jj * SROW + pp * 16;
        float mx = -3.0e38f;
#pragma unroll
        for (int q = 0; q < 4; ++q) {
            float4 v = *(const float4*)(row + 4 * q);
            v.x *= gv; v.y *= gv; v.z *= gv; v.w *= gv;
            mx = fmaxf(mx, fmaxf(fmaxf(v.x, v.y), fmaxf(v.z, v.w)));
            *(float4*)(row + 4 * q) = v;
        }
        out[(g0 + pp) * 160 + 32 + jj] = mx;
    }
    __syncthreads();

    // ---- last: out channels 0..31 = max_k (y3 @ Wlast + blast) -------------
    {
        ull a0 = 0ull, a1 = 0ull;
#pragma unroll 4
        for (int j = 0; j < 128; ++j) {
            const ulonglong2 av = *(const ulonglong2*)(sY2 + j * SROW + kk0);
            const float w = Wlast[(j << 5) + c];
            const ull wp = pack2(w, w);
            a0 = fma2(av.x, wp, a0);
            a1 = fma2(av.y, wp, a1);
        }
        const float bb = blast[c];
        const float2 v0 = unpack2(a0), v1 = unpack2(a1);
        const float mx = fmaxf(fmaxf(v0.x + bb, v0.y + bb),
                               fmaxf(v1.x + bb, v1.y + bb));
        sYbar[kq * 32 + c] = mx;        // reuse sYbar as reduce scratch
    }
    __syncthreads();
    if (t < 128) {
        const int p = t >> 5;
        const int cc = t & 31;
        float mx = sYbar[(4 * p + 0) * 32 + cc];
        mx = fmaxf(mx, sYbar[(4 * p + 1) * 32 + cc]);
        mx = fmaxf(mx, sYbar[(4 * p + 2) * 32 + cc]);
        mx = fmaxf(mx, sYbar[(4 * p + 3) * 32 + cc]);
        out[(g0 + p) * 160 + cc] = mx;
    }
}

// ---------------------------------------------------------------------------
extern "C" void kernel_launch(void* const* d_in, const int* in_sizes, int n_in,
                              void* d_out, int out_size) {
    const float* x = (const float*)d_in[0];
    const float* pos = (const float*)d_in[1];
    const float* W1 = (const float*)d_in[2];
    const float* b1 = (const float*)d_in[3];
    const float* W2 = (const float*)d_in[4];
    const float* b2 = (const float*)d_in[5];
    const float* Wmid = (const float*)d_in[6];
    const float* bmid = (const float*)d_in[7];
    const float* Wg = (const float*)d_in[8];
    const float* bg = (const float*)d_in[9];
    const float* Wlast = (const float*)d_in[10];
    const float* blast = (const float*)d_in[11];
    float* out = (float*)d_out;

    const int smem_bytes = SMEM_FLOATS * 4;
    cudaFuncSetAttribute(conv_kernel, cudaFuncAttributeMaxDynamicSharedMemorySize,
                         smem_bytes);

    prep_kernel<<<64, 256>>>(W1);
    knn_kernel<<<(Bb * Nn) / 128, 128>>>(pos);
    conv_kernel<<<(Bb * Nn) / P4, 512, smem_bytes>>>(
        x, b1, W2, b2, Wmid, bmid, Wg, bg, Wlast, blast, out);
}

// round 4
// speedup vs baseline: 1.3212x; 1.0165x over previous
#include <cuda_runtime.h>
#include <cuda_bf16.h>

#define Bb 8
#define Nn 4096
#define Dd 64
#define Gg 32
#define Kk 16

typedef unsigned long long ull;

// scratch
__device__ int g_nbr[Bb * Nn * Kk];
__device__ float g_W1p[64 * 256];   // W1[0:64] - W1[128:192]   (x part)
__device__ float g_W1n[64 * 256];   // W1[64:128] + W1[128:192] (nbr part)

// ---------------------------------------------------------------------------
// f32x2 packed-FMA helpers
// ---------------------------------------------------------------------------
__device__ __forceinline__ ull pack2(float a, float b) {
    ull r;
    asm("mov.b64 %0, {%1, %2};" : "=l"(r) : "f"(a), "f"(b));
    return r;
}
__device__ __forceinline__ ull fma2(ull a, ull b, ull c) {
    ull d;
    asm("fma.rn.f32x2 %0, %1, %2, %3;" : "=l"(d) : "l"(a), "l"(b), "l"(c));
    return d;
}
__device__ __forceinline__ float2 unpack2(ull v) {
    float2 f;
    asm("mov.b64 {%0, %1}, %2;" : "=f"(f.x), "=f"(f.y) : "l"(v));
    return f;
}

// ---------------------------------------------------------------------------
// Kernel 0: fold the 3-way edge concat into two 64-row weight blocks
// ---------------------------------------------------------------------------
__global__ __launch_bounds__(256) void prep_kernel(const float* __restrict__ W1) {
    const int i = blockIdx.x * 256 + threadIdx.x;   // 0..16383
    const int j = i >> 8;
    const int c = i & 255;
    const float wa = W1[j * 256 + c];
    const float wb = W1[(64 + j) * 256 + c];
    const float wc = W1[(128 + j) * 256 + c];
    g_W1p[i] = wa - wc;
    g_W1n[i] = wb + wc;
}

// ---------------------------------------------------------------------------
// Kernel 1: brute-force KNN (unchanged math from the passing version)
// ---------------------------------------------------------------------------
__global__ __launch_bounds__(128) void knn_kernel(const float* __restrict__ pos) {
    const int bx = blockIdx.x;
    const int b = bx >> 5;
    const int n = ((bx & 31) << 7) + threadIdx.x;

    const float qx = pos[(b * Nn + n) * 3 + 0];
    const float qy = pos[(b * Nn + n) * 3 + 1];
    const float qz = pos[(b * Nn + n) * 3 + 2];
    const float sqn = __fadd_rn(__fadd_rn(__fmul_rn(qx, qx), __fmul_rn(qy, qy)),
                                __fmul_rn(qz, qz));

    float bd[16];
    int bi[16];
#pragma unroll
    for (int j = 0; j < 16; ++j) { bd[j] = 3.0e38f; bi[j] = 0; }
    float worst = 3.0e38f;
    int wslot = 0;

    __shared__ float4 tile[1024];

    for (int t0 = 0; t0 < Nn; t0 += 1024) {
        __syncthreads();
        for (int i = threadIdx.x; i < 1024; i += 128) {
            const float px = pos[(b * Nn + t0 + i) * 3 + 0];
            const float py = pos[(b * Nn + t0 + i) * 3 + 1];
            const float pz = pos[(b * Nn + t0 + i) * 3 + 2];
            const float sq = __fadd_rn(__fadd_rn(__fmul_rn(px, px), __fmul_rn(py, py)),
                                       __fmul_rn(pz, pz));
            tile[i] = make_float4(px, py, pz, sq);
        }
        __syncthreads();
#pragma unroll 4
        for (int i = 0; i < 1024; ++i) {
            const float4 c = tile[i];
            const int m = t0 + i;
            float dot = __fmaf_rn(qx, c.x, 0.f);
            dot = __fmaf_rn(qy, c.y, dot);
            dot = __fmaf_rn(qz, c.z, dot);
            const float dist = __fsub_rn(__fadd_rn(sqn, c.w), __fmul_rn(2.0f, dot));
            if (dist < worst && m != n) {
#pragma unroll
                for (int j = 0; j < 16; ++j)
                    if (j == wslot) { bd[j] = dist; bi[j] = m; }
                worst = bd[0]; wslot = 0;
#pragma unroll
                for (int j = 1; j < 16; ++j)
                    if (bd[j] > worst) { worst = bd[j]; wslot = j; }
            }
        }
    }

#pragma unroll
    for (int j = 0; j < 16; ++j)
        g_nbr[(b * Nn + n) * 16 + j] = bi[j];
}

// ---------------------------------------------------------------------------
// Kernel 2: fused DenseEdgeConv, 2 points (32 k-lanes) per block, 256 threads,
// 67.6 KB smem -> 2 resident CTAs per SM for latency/barrier overlap.
// ---------------------------------------------------------------------------
#define SROW 36
#define P2 2

#define OFF_NBRT 0
#define OFF_H1   (OFF_NBRT + 64 * SROW)
#define OFF_Y2   (OFF_H1 + 256 * SROW)
#define OFF_XH   (OFF_Y2 + 128 * SROW)
#define OFF_XN   (OFF_XH + P2 * 256)
#define OFF_YBAR (OFF_XN + P2 * 64)
#define OFF_GATE (OFF_YBAR + P2 * 128)
#define OFF_NID  (OFF_GATE + P2 * 128)
#define SMEM_FLOATS (OFF_NID + 32)

__global__ __launch_bounds__(256, 2) void conv_kernel(
    const float* __restrict__ x,
    const float* __restrict__ b1,
    const float* __restrict__ W2, const float* __restrict__ b2,
    const float* __restrict__ Wmid, const float* __restrict__ bmid,
    const float* __restrict__ Wg, const float* __restrict__ bg,
    const float* __restrict__ Wlast, const float* __restrict__ blast,
    float* __restrict__ out)
{
    extern __shared__ float sm[];
    float* sNbrT = sm + OFF_NBRT;   // [64 j][SROW k]
    float* sH1 = sm + OFF_H1;       // [256 c][SROW k]
    float* sY2 = sm + OFF_Y2;       // [128 ch][SROW k]: 0..31 m, 32..63 h, 64..127 xn
    float* sXh = sm + OFF_XH;       // [2 p][256 c]
    float* sXn = sm + OFF_XN;
    float* sYbar = sm + OFF_YBAR;
    float* sGate = sm + OFF_GATE;
    int* sNid = (int*)(sm + OFF_NID);

    const int t = threadIdx.x;
    const int g0 = blockIdx.x * P2;
    const int b = g0 >> 12;

    if (t < 128) sXn[t] = x[(g0 + (t >> 6)) * 64 + (t & 63)];
    if (t < 32) sNid[t] = g_nbr[g0 * 16 + t];
    __syncthreads();

    // ---- gather neighbor features (transposed) + xn rows of y2 -----------
#pragma unroll
    for (int it = 0; it < 8; ++it) {
        const int idx = it * 256 + t;
        const int kk = idx >> 6;            // 0..31
        const int c = idx & 63;
        sNbrT[c * SROW + kk] = x[(b * Nn + sNid[kk]) * 64 + c];
        sY2[(64 + c) * SROW + kk] = sXn[(kk >> 4) * 64 + c];
    }

    // ---- x-part of GEMM1: sXh[p][c] = b1[c] + xn[p] . W1p[:,c] -----------
    {
        const int p = t >> 7;               // 0..1
        const int c0 = t & 127;
        float a0 = 0.f, a1 = 0.f;
        const float* xnp = sXn + p * 64;
#pragma unroll 8
        for (int j = 0; j < 64; ++j) {
            const float xv = xnp[j];
            a0 = __fmaf_rn(xv, g_W1p[j * 256 + c0], a0);
            a1 = __fmaf_rn(xv, g_W1p[j * 256 + c0 + 128], a1);
        }
        sXh[p * 256 + c0] = a0 + b1[c0];
        sXh[p * 256 + c0 + 128] = a1 + b1[c0 + 128];
    }
    __syncthreads();

    // ---- GEMM1 (nbr part): h1[c][kk] = relu(sXh + nbrT^T @ W1n) ----------
    // thread: 8 cols (cg) x 4 k (kq); warp = 4 cg x 8 kq
    {
        const int cg = t >> 3;              // 0..31
        const int kq = t & 7;               // 0..7
        const int kk0 = kq << 2;
        const int p = kq >> 2;              // 0..1
        ull acc[4][4];
#pragma unroll
        for (int cp = 0; cp < 4; ++cp)
#pragma unroll
            for (int k = 0; k < 4; ++k) acc[cp][k] = 0ull;

        const float* wb2 = g_W1n + cg * 8;
        const float* ab = sNbrT + kk0;
#pragma unroll 4
        for (int j = 0; j < 64; ++j) {
            const float4 av = *(const float4*)(ab + j * SROW);
            const ull a0 = pack2(av.x, av.x);
            const ull a1 = pack2(av.y, av.y);
            const ull a2 = pack2(av.z, av.z);
            const ull a3 = pack2(av.w, av.w);
            const ulonglong2 w01 = *(const ulonglong2*)(wb2 + j * 256);
            const ulonglong2 w23 = *(const ulonglong2*)(wb2 + j * 256 + 4);
            acc[0][0] = fma2(a0, w01.x, acc[0][0]);
            acc[0][1] = fma2(a1, w01.x, acc[0][1]);
            acc[0][2] = fma2(a2, w01.x, acc[0][2]);
            acc[0][3] = fma2(a3, w01.x, acc[0][3]);
            acc[1][0] = fma2(a0, w01.y, acc[1][0]);
            acc[1][1] = fma2(a1, w01.y, acc[1][1]);
            acc[1][2] = fma2(a2, w01.y, acc[1][2]);
            acc[1][3] = fma2(a3, w01.y, acc[1][3]);
            acc[2][0] = fma2(a0, w23.x, acc[2][0]);
            acc[2][1] = fma2(a1, w23.x, acc[2][1]);
            acc[2][2] = fma2(a2, w23.x, acc[2][2]);
            acc[2][3] = fma2(a3, w23.x, acc[2][3]);
            acc[3][0] = fma2(a0, w23.y, acc[3][0]);
            acc[3][1] = fma2(a1, w23.y, acc[3][1]);
            acc[3][2] = fma2(a2, w23.y, acc[3][2]);
            acc[3][3] = fma2(a3, w23.y, acc[3][3]);
        }
#pragma unroll
        for (int cp = 0; cp < 4; ++cp) {
            const int ce = cg * 8 + cp * 2;
            const float xhe = sXh[p * 256 + ce];
            const float xho = sXh[p * 256 + ce + 1];
            const float2 u0 = unpack2(acc[cp][0]);
            const float2 u1 = unpack2(acc[cp][1]);
            const float2 u2 = unpack2(acc[cp][2]);
            const float2 u3 = unpack2(acc[cp][3]);
            float4 ev, ov;
            ev.x = fmaxf(u0.x + xhe, 0.f); ev.y = fmaxf(u1.x + xhe, 0.f);
            ev.z = fmaxf(u2.x + xhe, 0.f); ev.w = fmaxf(u3.x + xhe, 0.f);
            ov.x = fmaxf(u0.y + xho, 0.f); ov.y = fmaxf(u1.y + xho, 0.f);
            ov.z = fmaxf(u2.y + xho, 0.f); ov.w = fmaxf(u3.y + xho, 0.f);
            *(float4*)(sH1 + ce * SROW + kk0) = ev;
            *(float4*)(sH1 + (ce + 1) * SROW + kk0) = ov;
        }
    }
    __syncthreads();

    const int c = t & 31;               // output channel (32)
    const int kq = t >> 5;              // 0..7
    const int kk0 = kq << 2;

    // ---- GEMM2: h = relu(h1^T @ W2 + b2) -> sY2 rows 32..63 ---------------
    {
        ull a0 = 0ull, a1 = 0ull;
#pragma unroll 4
        for (int j = 0; j < 256; ++j) {
            const ulonglong2 av = *(const ulonglong2*)(sH1 + j * SROW + kk0);
            const float w = W2[(j << 5) + c];
            const ull wp = pack2(w, w);
            a0 = fma2(av.x, wp, a0);
            a1 = fma2(av.y, wp, a1);
        }
        const float bb = b2[c];
        const float2 v0 = unpack2(a0), v1 = unpack2(a1);
        float4 r;
        r.x = fmaxf(v0.x + bb, 0.f); r.y = fmaxf(v0.y + bb, 0.f);
        r.z = fmaxf(v1.x + bb, 0.f); r.w = fmaxf(v1.y + bb, 0.f);
        *(float4*)(sY2 + (32 + c) * SROW + kk0) = r;
    }
    __syncthreads();

    // ---- mid: m = relu([h, xn] @ Wmid + bmid) -> sY2 rows 0..31 ------------
    {
        ull a0 = 0ull, a1 = 0ull;
#pragma unroll 4
        for (int j = 0; j < 96; ++j) {
            const ulonglong2 av = *(const ulonglong2*)(sY2 + (32 + j) * SROW + kk0);
            const float w = Wmid[(j << 5) + c];
            const ull wp = pack2(w, w);
            a0 = fma2(av.x, wp, a0);
            a1 = fma2(av.y, wp, a1);
        }
        const float bb = bmid[c];
        const float2 v0 = unpack2(a0), v1 = unpack2(a1);
        float4 r;
        r.x = fmaxf(v0.x + bb, 0.f); r.y = fmaxf(v0.y + bb, 0.f);
        r.z = fmaxf(v1.x + bb, 0.f); r.w = fmaxf(v1.y + bb, 0.f);
        *(float4*)(sY2 + c * SROW + kk0) = r;
    }
    __syncthreads();

    const int pp = t >> 7;              // 0..1
    const int jj = t & 127;

    // ---- ybar = mean_k y2 --------------------------------------------------
    {
        const float* row = sY2 + jj * SROW + pp * 16;
        const float4 s0 = *(const float4*)(row + 0);
        const float4 s1 = *(const float4*)(row + 4);
        const float4 s2 = *(const float4*)(row + 8);
        const float4 s3 = *(const float4*)(row + 12);
        const float s = (s0.x + s0.y + s0.z + s0.w) + (s1.x + s1.y + s1.z + s1.w)
                      + (s2.x + s2.y + s2.z + s2.w) + (s3.x + s3.y + s3.z + s3.w);
        sYbar[pp * 128 + jj] = s * (1.0f / 16.0f);
    }
    __syncthreads();

    // ---- gate = sigmoid(ybar @ Wg + bg) ------------------------------------
    {
        float a = 0.f;
        const float* yb = sYbar + pp * 128;
#pragma unroll 4
        for (int j = 0; j < 128; ++j)
            a = __fmaf_rn(yb[j], Wg[j * 128 + jj], a);
        a += bg[jj];
        sGate[pp * 128 + jj] = 1.0f / (1.0f + expf(-a));
    }
    __syncthreads();

    // ---- y2 *= gate; out channels 32..159 = max_k ---------------------------
    {
        const float gv = sGate[pp * 128 + jj];
        float* row = sY2 + jj * SROW + pp * 16;
        float mx = -3.0e38f;
#pragma unroll
        for (int q = 0; q < 4; ++q) {
            float4 v = *(const float4*)(row + 4 * q);
            v.x *= gv; v.y *= gv; v.z *= gv; v.w *= gv;
            mx = fmaxf(mx, fmaxf(fmaxf(v.x, v.y), fmaxf(v.z, v.w)));
            *(float4*)(row + 4 * q) = v;
        }
        out[(g0 + pp) * 160 + 32 + jj] = mx;
    }
    __syncthreads();

    // ---- last: out channels 0..31 = max_k (y3 @ Wlast + blast) -------------
    {
        ull a0 = 0ull, a1 = 0ull;
#pragma unroll 4
        for (int j = 0; j < 128; ++j) {
            const ulonglong2 av = *(const ulonglong2*)(sY2 + j * SROW + kk0);
            const float w = Wlast[(j << 5) + c];
            const ull wp = pack2(w, w);
            a0 = fma2(av.x, wp, a0);
            a1 = fma2(av.y, wp, a1);
        }
        const float bb = blast[c];
        const float2 v0 = unpack2(a0), v1 = unpack2(a1);
        const float mx = fmaxf(fmaxf(v0.x + bb, v0.y + bb),
                               fmaxf(v1.x + bb, v1.y + bb));
        sYbar[kq * 32 + c] = mx;        // reuse sYbar as reduce scratch
    }
    __syncthreads();
    if (t < 64) {
        const int p = t >> 5;           // 0..1
        const int cc = t & 31;
        float mx = sYbar[(4 * p + 0) * 32 + cc];
        mx = fmaxf(mx, sYbar[(4 * p + 1) * 32 + cc]);
        mx = fmaxf(mx, sYbar[(4 * p + 2) * 32 + cc]);
        mx = fmaxf(mx, sYbar[(4 * p + 3) * 32 + cc]);
        out[(g0 + p) * 160 + cc] = mx;
    }
}

// ---------------------------------------------------------------------------
extern "C" void kernel_launch(void* const* d_in, const int* in_sizes, int n_in,
                              void* d_out, int out_size) {
    const float* x = (const float*)d_in[0];
    const float* pos = (const float*)d_in[1];
    const float* W1 = (const float*)d_in[2];
    const float* b1 = (const float*)d_in[3];
    const float* W2 = (const float*)d_in[4];
    const float* b2 = (const float*)d_in[5];
    const float* Wmid = (const float*)d_in[6];
    const float* bmid = (const float*)d_in[7];
    const float* Wg = (const float*)d_in[8];
    const float* bg = (const float*)d_in[9];
    const float* Wlast = (const float*)d_in[10];
    const float* blast = (const float*)d_in[11];
    float* out = (float*)d_out;

    const int smem_bytes = SMEM_FLOATS * 4;
    cudaFuncSetAttribute(conv_kernel, cudaFuncAttributeMaxDynamicSharedMemorySize,
                         smem_bytes);

    prep_kernel<<<64, 256>>>(W1);
    knn_kernel<<<(Bb * Nn) / 128, 128>>>(pos);
    conv_kernel<<<(Bb * Nn) / P2, 256, smem_bytes>>>(
        x, b1, W2, b2, Wmid, bmid, Wg, bg, Wlast, blast, out);
}

// round 5
// speedup vs baseline: 1.7302x; 1.3096x over previous
#include <cuda_runtime.h>
#include <cuda_bf16.h>

#define Bb 8
#define Nn 4096
#define Dd 64
#define Gg 32
#define Kk 16

typedef unsigned long long ull;

// scratch
__device__ int g_nbr[Bb * Nn * Kk];
__device__ float g_W1p[64 * 256];   // W1[0:64] - W1[128:192]   (x part)
__device__ float g_W1n[64 * 256];   // W1[64:128] + W1[128:192] (nbr part)

// ---------------------------------------------------------------------------
// f32x2 packed-FMA helpers
// ---------------------------------------------------------------------------
__device__ __forceinline__ ull pack2(float a, float b) {
    ull r;
    asm("mov.b64 %0, {%1, %2};" : "=l"(r) : "f"(a), "f"(b));
    return r;
}
__device__ __forceinline__ ull fma2(ull a, ull b, ull c) {
    ull d;
    asm("fma.rn.f32x2 %0, %1, %2, %3;" : "=l"(d) : "l"(a), "l"(b), "l"(c));
    return d;
}
__device__ __forceinline__ float2 unpack2(ull v) {
    float2 f;
    asm("mov.b64 {%0, %1}, %2;" : "=f"(f.x), "=f"(f.y) : "l"(v));
    return f;
}

// ---------------------------------------------------------------------------
// Kernel 1: KNN (blocks 0..255) + W1 fold (blocks 256..383). 2-launch sequence
// so ncu -s 5 lands on conv_kernel.
// ---------------------------------------------------------------------------
__global__ __launch_bounds__(128) void knn_prep_kernel(const float* __restrict__ pos,
                                                       const float* __restrict__ W1) {
    const int bx = blockIdx.x;
    if (bx >= 256) {
        // prep: fold 3-way edge concat into two 64-row weight blocks
        const int i = (bx - 256) * 128 + threadIdx.x;   // 0..16383
        const int j = i >> 8;
        const int c = i & 255;
        const float wa = W1[j * 256 + c];
        const float wb = W1[(64 + j) * 256 + c];
        const float wc = W1[(128 + j) * 256 + c];
        g_W1p[i] = wa - wc;
        g_W1n[i] = wb + wc;
        return;
    }

    const int b = bx >> 5;
    const int n = ((bx & 31) << 7) + threadIdx.x;

    const float qx = pos[(b * Nn + n) * 3 + 0];
    const float qy = pos[(b * Nn + n) * 3 + 1];
    const float qz = pos[(b * Nn + n) * 3 + 2];
    const float sqn = __fadd_rn(__fadd_rn(__fmul_rn(qx, qx), __fmul_rn(qy, qy)),
                                __fmul_rn(qz, qz));

    float bd[16];
    int bi[16];
#pragma unroll
    for (int j = 0; j < 16; ++j) { bd[j] = 3.0e38f; bi[j] = 0; }
    float worst = 3.0e38f;
    int wslot = 0;

    __shared__ float4 tile[1024];

    for (int t0 = 0; t0 < Nn; t0 += 1024) {
        __syncthreads();
        for (int i = threadIdx.x; i < 1024; i += 128) {
            const float px = pos[(b * Nn + t0 + i) * 3 + 0];
            const float py = pos[(b * Nn + t0 + i) * 3 + 1];
            const float pz = pos[(b * Nn + t0 + i) * 3 + 2];
            const float sq = __fadd_rn(__fadd_rn(__fmul_rn(px, px), __fmul_rn(py, py)),
                                       __fmul_rn(pz, pz));
            tile[i] = make_float4(px, py, pz, sq);
        }
        __syncthreads();
#pragma unroll 4
        for (int i = 0; i < 1024; ++i) {
            const float4 c = tile[i];
            const int m = t0 + i;
            float dot = __fmaf_rn(qx, c.x, 0.f);
            dot = __fmaf_rn(qy, c.y, dot);
            dot = __fmaf_rn(qz, c.z, dot);
            const float dist = __fsub_rn(__fadd_rn(sqn, c.w), __fmul_rn(2.0f, dot));
            if (dist < worst && m != n) {
#pragma unroll
                for (int j = 0; j < 16; ++j)
                    if (j == wslot) { bd[j] = dist; bi[j] = m; }
                worst = bd[0]; wslot = 0;
#pragma unroll
                for (int j = 1; j < 16; ++j)
                    if (bd[j] > worst) { worst = bd[j]; wslot = j; }
            }
        }
    }

#pragma unroll
    for (int j = 0; j < 16; ++j)
        g_nbr[(b * Nn + n) * 16 + j] = bi[j];
}

// ---------------------------------------------------------------------------
// Kernel 2: fused DenseEdgeConv. 2 points (32 k-lanes), 128 threads, 3 CTAs/SM.
// Deep per-thread tiles: every thread owns 8 k-lanes in every GEMM stage.
// ---------------------------------------------------------------------------
#define SROW 36
#define P2 2

#define OFF_NBRT 0
#define OFF_H1   (OFF_NBRT + 64 * SROW)
#define OFF_Y2   (OFF_H1 + 256 * SROW)
#define OFF_XH   (OFF_Y2 + 128 * SROW)
#define OFF_XN   (OFF_XH + P2 * 256)
#define OFF_YBAR (OFF_XN + P2 * 64)
#define OFF_GATE (OFF_YBAR + P2 * 128)
#define OFF_NID  (OFF_GATE + P2 * 128)
#define SMEM_FLOATS (OFF_NID + 32)

__global__ __launch_bounds__(128, 3) void conv_kernel(
    const float* __restrict__ x,
    const float* __restrict__ b1,
    const float* __restrict__ W2, const float* __restrict__ b2,
    const float* __restrict__ Wmid, const float* __restrict__ bmid,
    const float* __restrict__ Wg, const float* __restrict__ bg,
    const float* __restrict__ Wlast, const float* __restrict__ blast,
    float* __restrict__ out)
{
    extern __shared__ float sm[];
    float* sNbrT = sm + OFF_NBRT;   // [64 j][SROW k]
    float* sH1 = sm + OFF_H1;       // [256 c][SROW k]
    float* sY2 = sm + OFF_Y2;       // [128 ch][SROW k]: 0..31 m, 32..63 h, 64..127 xn
    float* sXh = sm + OFF_XH;       // [2 p][256 c]
    float* sXn = sm + OFF_XN;       // [2 p][64 c]
    float* sYbar = sm + OFF_YBAR;   // [2 p][128]
    float* sGate = sm + OFF_GATE;   // [2 p][128]
    int* sNid = (int*)(sm + OFF_NID);

    const int t = threadIdx.x;
    const int g0 = blockIdx.x * P2;
    const int b = g0 >> 12;

    sXn[t] = x[(g0 + (t >> 6)) * 64 + (t & 63)];
    if (t < 32) sNid[t] = g_nbr[g0 * 16 + t];
    __syncthreads();

    // ---- gather neighbor features (transposed) + xn rows of y2 -----------
#pragma unroll
    for (int it = 0; it < 16; ++it) {
        const int idx = it * 128 + t;
        const int kk = idx >> 6;            // 0..31
        const int c = idx & 63;
        sNbrT[c * SROW + kk] = x[(b * Nn + sNid[kk]) * 64 + c];
        sY2[(64 + c) * SROW + kk] = sXn[(kk >> 4) * 64 + c];
    }

    // ---- x-part of GEMM1: sXh[p][c] = b1[c] + xn[p] . W1p[:,c] -----------
    // thread = column c0 and c0+128; both points share the weight loads.
    {
        const int c0 = t;                   // 0..127
        float a00 = 0.f, a01 = 0.f, a10 = 0.f, a11 = 0.f;
#pragma unroll 8
        for (int j = 0; j < 64; ++j) {
            const float w0 = g_W1p[j * 256 + c0];
            const float w1 = g_W1p[j * 256 + c0 + 128];
            const float x0 = sXn[j];
            const float x1 = sXn[64 + j];
            a00 = __fmaf_rn(x0, w0, a00);
            a01 = __fmaf_rn(x0, w1, a01);
            a10 = __fmaf_rn(x1, w0, a10);
            a11 = __fmaf_rn(x1, w1, a11);
        }
        const float bb0 = b1[c0];
        const float bb1 = b1[c0 + 128];
        sXh[c0] = a00 + bb0;
        sXh[c0 + 128] = a01 + bb1;
        sXh[256 + c0] = a10 + bb0;
        sXh[256 + c0 + 128] = a11 + bb1;
    }
    __syncthreads();

    // ---- GEMM1 (nbr part): h1[c][kk] = relu(sXh + nbrT^T @ W1n) ----------
    // thread: 8 cols x 8 k (k-pairs packed in f32x2 accumulators)
    {
        const int cg = t >> 2;              // 0..31 -> cols cg*8..cg*8+7
        const int kg = t & 3;               // 0..3  -> k kg*8..kg*8+7
        const int kk0 = kg << 3;
        const int p = kg >> 1;
        ull acc[8][4];
#pragma unroll
        for (int c = 0; c < 8; ++c)
#pragma unroll
            for (int kp = 0; kp < 4; ++kp) acc[c][kp] = 0ull;

        const float* wb = g_W1n + cg * 8;
        const float* ab = sNbrT + kk0;
#pragma unroll 4
        for (int j = 0; j < 64; ++j) {
            const float4 w0 = *(const float4*)(wb + j * 256);
            const float4 w1 = *(const float4*)(wb + j * 256 + 4);
            ull wp[8];
            wp[0] = pack2(w0.x, w0.x); wp[1] = pack2(w0.y, w0.y);
            wp[2] = pack2(w0.z, w0.z); wp[3] = pack2(w0.w, w0.w);
            wp[4] = pack2(w1.x, w1.x); wp[5] = pack2(w1.y, w1.y);
            wp[6] = pack2(w1.z, w1.z); wp[7] = pack2(w1.w, w1.w);
            const ulonglong2 a01 = *(const ulonglong2*)(ab + j * SROW);
            const ulonglong2 a23 = *(const ulonglong2*)(ab + j * SROW + 4);
#pragma unroll
            for (int c = 0; c < 8; ++c) {
                acc[c][0] = fma2(a01.x, wp[c], acc[c][0]);
                acc[c][1] = fma2(a01.y, wp[c], acc[c][1]);
                acc[c][2] = fma2(a23.x, wp[c], acc[c][2]);
                acc[c][3] = fma2(a23.y, wp[c], acc[c][3]);
            }
        }
#pragma unroll
        for (int c = 0; c < 8; ++c) {
            const int ce = cg * 8 + c;
            const float xhv = sXh[p * 256 + ce];
            const float2 u0 = unpack2(acc[c][0]);
            const float2 u1 = unpack2(acc[c][1]);
            const float2 u2 = unpack2(acc[c][2]);
            const float2 u3 = unpack2(acc[c][3]);
            float4 r0, r1;
            r0.x = fmaxf(u0.x + xhv, 0.f); r0.y = fmaxf(u0.y + xhv, 0.f);
            r0.z = fmaxf(u1.x + xhv, 0.f); r0.w = fmaxf(u1.y + xhv, 0.f);
            r1.x = fmaxf(u2.x + xhv, 0.f); r1.y = fmaxf(u2.y + xhv, 0.f);
            r1.z = fmaxf(u3.x + xhv, 0.f); r1.w = fmaxf(u3.y + xhv, 0.f);
            *(float4*)(sH1 + ce * SROW + kk0) = r0;
            *(float4*)(sH1 + ce * SROW + kk0 + 4) = r1;
        }
    }
    __syncthreads();

    const int c = t & 31;               // output channel (32)
    const int kq = t >> 5;              // 0..3 -> 8 k each
    const int kk0 = kq << 3;

    // ---- GEMM2: h = relu(h1^T @ W2 + b2) -> sY2 rows 32..63 ---------------
    {
        ull a0 = 0ull, a1 = 0ull, a2 = 0ull, a3 = 0ull;
#pragma unroll 4
        for (int j = 0; j < 256; ++j) {
            const ulonglong2 v01 = *(const ulonglong2*)(sH1 + j * SROW + kk0);
            const ulonglong2 v23 = *(const ulonglong2*)(sH1 + j * SROW + kk0 + 4);
            const float w = W2[(j << 5) + c];
            const ull wp = pack2(w, w);
            a0 = fma2(v01.x, wp, a0);
            a1 = fma2(v01.y, wp, a1);
            a2 = fma2(v23.x, wp, a2);
            a3 = fma2(v23.y, wp, a3);
        }
        const float bb = b2[c];
        const float2 u0 = unpack2(a0), u1 = unpack2(a1);
        const float2 u2 = unpack2(a2), u3 = unpack2(a3);
        float4 r0, r1;
        r0.x = fmaxf(u0.x + bb, 0.f); r0.y = fmaxf(u0.y + bb, 0.f);
        r0.z = fmaxf(u1.x + bb, 0.f); r0.w = fmaxf(u1.y + bb, 0.f);
        r1.x = fmaxf(u2.x + bb, 0.f); r1.y = fmaxf(u2.y + bb, 0.f);
        r1.z = fmaxf(u3.x + bb, 0.f); r1.w = fmaxf(u3.y + bb, 0.f);
        *(float4*)(sY2 + (32 + c) * SROW + kk0) = r0;
        *(float4*)(sY2 + (32 + c) * SROW + kk0 + 4) = r1;
    }
    __syncthreads();

    // ---- mid: m = relu([h, xn] @ Wmid + bmid) -> sY2 rows 0..31 ------------
    {
        ull a0 = 0ull, a1 = 0ull, a2 = 0ull, a3 = 0ull;
#pragma unroll 4
        for (int j = 0; j < 96; ++j) {
            const ulonglong2 v01 = *(const ulonglong2*)(sY2 + (32 + j) * SROW + kk0);
            const ulonglong2 v23 = *(const ulonglong2*)(sY2 + (32 + j) * SROW + kk0 + 4);
            const float w = Wmid[(j << 5) + c];
            const ull wp = pack2(w, w);
            a0 = fma2(v01.x, wp, a0);
            a1 = fma2(v01.y, wp, a1);
            a2 = fma2(v23.x, wp, a2);
            a3 = fma2(v23.y, wp, a3);
        }
        const float bb = bmid[c];
        const float2 u0 = unpack2(a0), u1 = unpack2(a1);
        const float2 u2 = unpack2(a2), u3 = unpack2(a3);
        float4 r0, r1;
        r0.x = fmaxf(u0.x + bb, 0.f); r0.y = fmaxf(u0.y + bb, 0.f);
        r0.z = fmaxf(u1.x + bb, 0.f); r0.w = fmaxf(u1.y + bb, 0.f);
        r1.x = fmaxf(u2.x + bb, 0.f); r1.y = fmaxf(u2.y + bb, 0.f);
        r1.z = fmaxf(u3.x + bb, 0.f); r1.w = fmaxf(u3.y + bb, 0.f);
        *(float4*)(sY2 + c * SROW + kk0) = r0;
        *(float4*)(sY2 + c * SROW + kk0 + 4) = r1;
    }
    __syncthreads();

    // ---- ybar = mean_k y2 (thread = channel jj, loop over points) ---------
    {
        const int jj = t;
#pragma unroll
        for (int pp = 0; pp < 2; ++pp) {
            const float* row = sY2 + jj * SROW + pp * 16;
            const float4 s0 = *(const float4*)(row + 0);
            const float4 s1 = *(const float4*)(row + 4);
            const float4 s2 = *(const float4*)(row + 8);
            const float4 s3 = *(const float4*)(row + 12);
            const float s = (s0.x + s0.y + s0.z + s0.w) + (s1.x + s1.y + s1.z + s1.w)
                          + (s2.x + s2.y + s2.z + s2.w) + (s3.x + s3.y + s3.z + s3.w);
            sYbar[pp * 128 + jj] = s * (1.0f / 16.0f);
        }
    }
    __syncthreads();

    // ---- gate = sigmoid(ybar @ Wg + bg); weight shared across points ------
    {
        const int jj = t;
        float a0 = 0.f, a1 = 0.f;
#pragma unroll 4
        for (int j = 0; j < 128; ++j) {
            const float w = Wg[j * 128 + jj];
            a0 = __fmaf_rn(sYbar[j], w, a0);
            a1 = __fmaf_rn(sYbar[128 + j], w, a1);
        }
        const float bb = bg[jj];
        sGate[jj] = 1.0f / (1.0f + expf(-(a0 + bb)));
        sGate[128 + jj] = 1.0f / (1.0f + expf(-(a1 + bb)));
    }
    __syncthreads();

    // ---- y2 *= gate; out channels 32..159 = max_k ---------------------------
    {
        const int jj = t;
#pragma unroll
        for (int pp = 0; pp < 2; ++pp) {
            const float gv = sGate[pp * 128 + jj];
            float* row = sY2 + jj * SROW + pp * 16;
            float mx = -3.0e38f;
#pragma unroll
            for (int q = 0; q < 4; ++q) {
                float4 v = *(const float4*)(row + 4 * q);
                v.x *= gv; v.y *= gv; v.z *= gv; v.w *= gv;
                mx = fmaxf(mx, fmaxf(fmaxf(v.x, v.y), fmaxf(v.z, v.w)));
                *(float4*)(row + 4 * q) = v;
            }
            out[(g0 + pp) * 160 + 32 + jj] = mx;
        }
    }
    __syncthreads();

    // ---- last: out channels 0..31 = max_k (y3 @ Wlast + blast) -------------
    {
        ull a0 = 0ull, a1 = 0ull, a2 = 0ull, a3 = 0ull;
#pragma unroll 4
        for (int j = 0; j < 128; ++j) {
            const ulonglong2 v01 = *(const ulonglong2*)(sY2 + j * SROW + kk0);
            const ulonglong2 v23 = *(const ulonglong2*)(sY2 + j * SROW + kk0 + 4);
            const float w = Wlast[(j << 5) + c];
            const ull wp = pack2(w, w);
            a0 = fma2(v01.x, wp, a0);
            a1 = fma2(v01.y, wp, a1);
            a2 = fma2(v23.x, wp, a2);
            a3 = fma2(v23.y, wp, a3);
        }
        const float bb = blast[c];
        const float2 u0 = unpack2(a0), u1 = unpack2(a1);
        const float2 u2 = unpack2(a2), u3 = unpack2(a3);
        float mx = fmaxf(fmaxf(u0.x + bb, u0.y + bb), fmaxf(u1.x + bb, u1.y + bb));
        mx = fmaxf(mx, fmaxf(fmaxf(u2.x + bb, u2.y + bb), fmaxf(u3.x + bb, u3.y + bb)));
        sYbar[kq * 32 + c] = mx;        // reuse sYbar as reduce scratch
    }
    __syncthreads();
    if (t < 64) {
        const int p = t >> 5;           // 0..1
        const int cc = t & 31;
        const float mx = fmaxf(sYbar[(2 * p + 0) * 32 + cc],
                               sYbar[(2 * p + 1) * 32 + cc]);
        out[(g0 + p) * 160 + cc] = mx;
    }
}

// ---------------------------------------------------------------------------
extern "C" void kernel_launch(void* const* d_in, const int* in_sizes, int n_in,
                              void* d_out, int out_size) {
    const float* x = (const float*)d_in[0];
    const float* pos = (const float*)d_in[1];
    const float* W1 = (const float*)d_in[2];
    const float* b1 = (const float*)d_in[3];
    const float* W2 = (const float*)d_in[4];
    const float* b2 = (const float*)d_in[5];
    const float* Wmid = (const float*)d_in[6];
    const float* bmid = (const float*)d_in[7];
    const float* Wg = (const float*)d_in[8];
    const float* bg = (const float*)d_in[9];
    const float* Wlast = (const float*)d_in[10];
    const float* blast = (const float*)d_in[11];
    float* out = (float*)d_out;

    const int smem_bytes = SMEM_FLOATS * 4;
    cudaFuncSetAttribute(conv_kernel, cudaFuncAttributeMaxDynamicSharedMemorySize,
                         smem_bytes);

    knn_prep_kernel<<<256 + 128, 128>>>(pos, W1);
    conv_kernel<<<(Bb * Nn) / P2, 128, smem_bytes>>>(
        x, b1, W2, b2, Wmid, bmid, Wg, bg, Wlast, blast, out);
}